// round 15
// baseline (speedup 1.0000x reference)
#include <cuda_runtime.h>
#include <math.h>
#include <stdint.h>

// Problem constants
#define NB 2
#define NS 1024
#define ND 512
#define NH 8
#define NCAT 2688           // 3*512 + 3*384
#define NCD 112             // 64 + 48
#define NBH 16              // NB*NH
#define NROWS 2048          // NB*NS
#define ATT_W 896           // ND + NHP3

// Fused attention tiling (R6 exact)
#define FBM 128
#define FBK 64
#define QS_LD 132
#define KS_LD 68
#define VS_LD 116
#define PS_LD 130

// Scratch (static device memory; no runtime allocation)
__device__ float g_xn[NROWS * ND];
__device__ float g_Qc[NBH * NS * NCD];
__device__ float g_Kc[NBH * NS * NCD];
__device__ float g_Vc[NBH * NS * NCD];
__device__ float g_qn2[NBH * NS];
__device__ float g_kn2[NBH * NS];
__device__ float g_att[NROWS * ATT_W];
__device__ float g_pre[NROWS * ND];

// ---------------- f32x2 packed helpers ----------------
__device__ __forceinline__ unsigned long long dup2(float x) {
    unsigned long long r; unsigned u = __float_as_uint(x);
    asm("mov.b64 %0, {%1, %1};" : "=l"(r) : "r"(u));
    return r;
}
__device__ __forceinline__ unsigned long long pack2(float lo, float hi) {
    unsigned long long r;
    asm("mov.b64 %0, {%1, %2};" : "=l"(r) : "r"(__float_as_uint(lo)), "r"(__float_as_uint(hi)));
    return r;
}
__device__ __forceinline__ void ffma2(unsigned long long& c, unsigned long long a, unsigned long long b) {
    asm("fma.rn.f32x2 %0, %1, %2, %0;" : "+l"(c) : "l"(a), "l"(b));
}
__device__ __forceinline__ void mul2(unsigned long long& c, unsigned long long a) {
    asm("mul.rn.f32x2 %0, %0, %1;" : "+l"(c) : "l"(a));
}
__device__ __forceinline__ void unpk(unsigned long long v, float& lo, float& hi) {
    unsigned a, b;
    asm("mov.b64 {%0, %1}, %2;" : "=r"(a), "=r"(b) : "l"(v));
    lo = __uint_as_float(a); hi = __uint_as_float(b);
}
__device__ __forceinline__ void cpasync16(uint32_t dst, const void* src) {
    asm volatile("cp.async.cg.shared.global [%0], [%1], 16;" :: "r"(dst), "l"(src));
}
#define CP_COMMIT() asm volatile("cp.async.commit_group;")
#define CP_WAIT1()  asm volatile("cp.async.wait_group 1;")

// ---------------- LayerNorm (optionally with residual add), shuffle-based ----------------
__global__ void k_ln(const float* __restrict__ x, const float* __restrict__ res,
                     const float* __restrict__ g, const float* __restrict__ b,
                     float* __restrict__ y) {
    int row = blockIdx.x, tid = threadIdx.x;
    const float* xr = x + (size_t)row * ND;
    float v0 = xr[tid], v1 = xr[tid + 256];
    if (res) {
        v0 += res[(size_t)row * ND + tid];
        v1 += res[(size_t)row * ND + tid + 256];
    }
    __shared__ float ws[8], ws2[8];
    float s = v0 + v1;
#pragma unroll
    for (int o = 16; o > 0; o >>= 1) s += __shfl_xor_sync(0xffffffffu, s, o);
    if ((tid & 31) == 0) ws[tid >> 5] = s;
    __syncthreads();
    float tot = ws[0] + ws[1] + ws[2] + ws[3] + ws[4] + ws[5] + ws[6] + ws[7];
    float mean = tot * (1.0f / ND);
    float d0 = v0 - mean, d1 = v1 - mean;
    float s2 = d0 * d0 + d1 * d1;
#pragma unroll
    for (int o = 16; o > 0; o >>= 1) s2 += __shfl_xor_sync(0xffffffffu, s2, o);
    if ((tid & 31) == 0) ws2[tid >> 5] = s2;
    __syncthreads();
    float tv = ws2[0] + ws2[1] + ws2[2] + ws2[3] + ws2[4] + ws2[5] + ws2[6] + ws2[7];
    float rstd = rsqrtf(tv * (1.0f / ND) + 1e-5f);
    float* yr = y + (size_t)row * ND;
    yr[tid]       = d0 * rstd * g[tid] + b[tid];
    yr[tid + 256] = d1 * rstd * g[tid + 256] + b[tid + 256];
}

// ---------------- Scatter a PAIR (c even) of projection outputs as one u64 store --------
__device__ __forceinline__ void scatter_proj2(
    int b, int s, int r, int c, float lo, float hi, const float* __restrict__ coords,
    const float* __restrict__ bqp, const float* __restrict__ bkp, const float* __restrict__ bvp)
{
    if (c < 1536) {
        int seg = c >> 9;
        int cc = c & 511;
        int h = cc >> 6, j = cc & 63;                 // j even; j,j+1 same head
        size_t o = ((size_t)(b * NH + h) * NS + s) * NCD + j;
        if (seg == 0) { lo *= 0.125f; hi *= 0.125f;   // SCALE = 1/8
            *(unsigned long long*)(g_Qc + o) = pack2(lo, hi);
        } else if (seg == 1) {
            *(unsigned long long*)(g_Kc + o) = pack2(lo, hi);
        } else {
            *(unsigned long long*)(g_Vc + o) = pack2(lo, hi);
        }
    } else {
        int t = c - 1536;
        int seg = t / 384;
        int cc = t - seg * 384;
        int h = cc / 48, jj = cc - h * 48;            // jj even; jj,jj+1 same head
        size_t o = ((size_t)(b * NH + h) * NS + s) * NCD + 64 + jj;
        if (seg == 0) {
            lo += bqp[cc]     + coords[r * 3 + (jj % 3)];
            hi += bqp[cc + 1] + coords[r * 3 + ((jj + 1) % 3)];
            *(unsigned long long*)(g_Qc + o) = pack2(lo, hi);
        } else if (seg == 1) {
            lo += bkp[cc]     + coords[r * 3 + (jj % 3)];
            hi += bkp[cc + 1] + coords[r * 3 + ((jj + 1) % 3)];
            *(unsigned long long*)(g_Kc + o) = pack2(lo, hi);
        } else {
            lo += bvp[cc];
            hi += bvp[cc + 1];
            *(unsigned long long*)(g_Vc + o) = pack2(lo, hi);
        }
    }
}

// ---------------- Projection GEMM v3: 64x64 tiles (gemm_out recipe), occ 4 --------------
// M=2048, logical N=2688, K=512. 256 threads, 4x4/thread, scatter epilogue.
// Segment boundaries (512,1024,1536,1920,2304) are all multiples of 64 -> CTA-uniform.
__global__ void __launch_bounds__(256, 4)
k_proj(const float* __restrict__ coords,
       const float* __restrict__ Wq, const float* __restrict__ Wk, const float* __restrict__ Wv,
       const float* __restrict__ Wqp, const float* __restrict__ Wkp, const float* __restrict__ Wvp,
       const float* __restrict__ bqp, const float* __restrict__ bkp, const float* __restrict__ bvp)
{
    const float* A = g_xn;
    __shared__ float As[2][16][68];
    __shared__ float Bs[2][16][64];
    const int tid = threadIdx.x;
    const int tn = tid & 15, tm = tid >> 4;
    const int m0 = tm * 4, n0 = tn * 4;
    const int rb = blockIdx.y * 64, cb = blockIdx.x * 64;

    const float* W; int ldw, coff;
    if      (cb < 512)  { W = Wq;  ldw = 512; coff = cb; }
    else if (cb < 1024) { W = Wk;  ldw = 512; coff = cb - 512; }
    else if (cb < 1536) { W = Wv;  ldw = 512; coff = cb - 1024; }
    else if (cb < 1920) { W = Wqp; ldw = 384; coff = cb - 1536; }
    else if (cb < 2304) { W = Wkp; ldw = 384; coff = cb - 1920; }
    else                { W = Wvp; ldw = 384; coff = cb - 2304; }

    unsigned long long acc[4][2];
#pragma unroll
    for (int i = 0; i < 4; i++) { acc[i][0] = 0ull; acc[i][1] = 0ull; }

    const int aR = tid >> 2, aC = (tid & 3) * 4;      // A tile 64x16, 1 float4/thread
    const int bR = tid >> 4, bC = (tid & 15) * 4;     // B tile 16x64, 1 float4/thread

    float4 av, bv;
    av = *(const float4*)(A + (size_t)(rb + aR) * ND + aC);
    bv = *(const float4*)(W + (size_t)bR * ldw + coff + bC);
    As[0][aC + 0][aR] = av.x; As[0][aC + 1][aR] = av.y;
    As[0][aC + 2][aR] = av.z; As[0][aC + 3][aR] = av.w;
    *(float4*)&Bs[0][bR][bC] = bv;
    __syncthreads();

    int buf = 0;
    for (int k0 = 0; k0 < ND; k0 += 16) {
        const bool nxt = (k0 + 16) < ND;
        if (nxt) {
            av = *(const float4*)(A + (size_t)(rb + aR) * ND + k0 + 16 + aC);
            bv = *(const float4*)(W + (size_t)(k0 + 16 + bR) * ldw + coff + bC);
        }
#pragma unroll
        for (int kk = 0; kk < 16; kk++) {
            unsigned long long bb0 = *(const unsigned long long*)&Bs[buf][kk][n0];
            unsigned long long bb1 = *(const unsigned long long*)&Bs[buf][kk][n0 + 2];
#pragma unroll
            for (int i = 0; i < 4; i++) {
                unsigned long long ad = dup2(As[buf][kk][m0 + i]);
                ffma2(acc[i][0], ad, bb0);
                ffma2(acc[i][1], ad, bb1);
            }
        }
        if (nxt) {
            int nb = buf ^ 1;
            As[nb][aC + 0][aR] = av.x; As[nb][aC + 1][aR] = av.y;
            As[nb][aC + 2][aR] = av.z; As[nb][aC + 3][aR] = av.w;
            *(float4*)&Bs[nb][bR][bC] = bv;
            __syncthreads();
            buf = nb;
        }
    }

#pragma unroll
    for (int i = 0; i < 4; i++) {
        int r = rb + m0 + i;
        int b = r >> 10, s = r & 1023;
        float l0, h0, l1, h1;
        unpk(acc[i][0], l0, h0); unpk(acc[i][1], l1, h1);
        scatter_proj2(b, s, r, cb + n0,     l0, h0, coords, bqp, bkp, bvp);
        scatter_proj2(b, s, r, cb + n0 + 2, l1, h1, coords, bqp, bkp, bvp);
    }
}

// ---------------- Output projection GEMM: 64x64 tile, occ 4, 256 CTAs ----------------
__global__ void __launch_bounds__(256, 4)
gemm_out(const float* __restrict__ A, const float* __restrict__ B,
         const float* __restrict__ bias, float* __restrict__ C)
{
    const int N = ND, K = ATT_W;
    __shared__ float As[2][16][68];
    __shared__ float Bs[2][16][64];
    const int tid = threadIdx.x;
    const int tn = tid & 15, tm = tid >> 4;
    const int m0 = tm * 4, n0 = tn * 4;
    const int rb = blockIdx.y * 64, cb = blockIdx.x * 64;

    unsigned long long acc[4][2];
#pragma unroll
    for (int i = 0; i < 4; i++) { acc[i][0] = 0ull; acc[i][1] = 0ull; }

    const int aR = tid >> 2, aC = (tid & 3) * 4;
    const int bR = tid >> 4, bC = (tid & 15) * 4;

    float4 av, bv;
    av = *(const float4*)(A + (size_t)(rb + aR) * K + aC);
    bv = *(const float4*)(B + (size_t)bR * N + cb + bC);
    As[0][aC + 0][aR] = av.x; As[0][aC + 1][aR] = av.y;
    As[0][aC + 2][aR] = av.z; As[0][aC + 3][aR] = av.w;
    *(float4*)&Bs[0][bR][bC] = bv;
    __syncthreads();

    int buf = 0;
    for (int k0 = 0; k0 < K; k0 += 16) {
        const bool nxt = (k0 + 16) < K;
        if (nxt) {
            av = *(const float4*)(A + (size_t)(rb + aR) * K + k0 + 16 + aC);
            bv = *(const float4*)(B + (size_t)(k0 + 16 + bR) * N + cb + bC);
        }
#pragma unroll
        for (int kk = 0; kk < 16; kk++) {
            unsigned long long bb0 = *(const unsigned long long*)&Bs[buf][kk][n0];
            unsigned long long bb1 = *(const unsigned long long*)&Bs[buf][kk][n0 + 2];
#pragma unroll
            for (int i = 0; i < 4; i++) {
                unsigned long long ad = dup2(As[buf][kk][m0 + i]);
                ffma2(acc[i][0], ad, bb0);
                ffma2(acc[i][1], ad, bb1);
            }
        }
        if (nxt) {
            int nb = buf ^ 1;
            As[nb][aC + 0][aR] = av.x; As[nb][aC + 1][aR] = av.y;
            As[nb][aC + 2][aR] = av.z; As[nb][aC + 3][aR] = av.w;
            *(float4*)&Bs[nb][bR][bC] = bv;
            __syncthreads();
            buf = nb;
        }
    }

#pragma unroll
    for (int i = 0; i < 4; i++) {
        int r = rb + m0 + i;
        int c = cb + n0;
        float l0, h0, l1, h1;
        unpk(acc[i][0], l0, h0); unpk(acc[i][1], l1, h1);
        l0 += bias[c];     h0 += bias[c + 1];
        l1 += bias[c + 2]; h1 += bias[c + 3];
        *(unsigned long long*)(C + (size_t)r * N + c)     = pack2(l0, h0);
        *(unsigned long long*)(C + (size_t)r * N + c + 2) = pack2(l1, h1);
    }
}

// ---------------- Point norms ----------------
__global__ void k_norms() {
    int t = threadIdx.x;
    int r = blockIdx.x * 8 + (t >> 5);
    int lane = t & 31;
    const float* q = g_Qc + (size_t)r * NCD + 64;
    const float* k = g_Kc + (size_t)r * NCD + 64;
    float qa = q[lane], ka = k[lane];
    float qb = 0.f, kb = 0.f;
    if (lane < 16) { qb = q[32 + lane]; kb = k[32 + lane]; }
    float qs = qa * qa + qb * qb;
    float ks = ka * ka + kb * kb;
#pragma unroll
    for (int o = 16; o > 0; o >>= 1) {
        qs += __shfl_xor_sync(0xffffffffu, qs, o);
        ks += __shfl_xor_sync(0xffffffffu, ks, o);
    }
    if (lane == 0) { g_qn2[r] = qs; g_kn2[r] = ks; }
}

// ---------------- Fused attention (EXACT R6 — measured 283us) ----------------------------
__global__ void __launch_bounds__(512, 1)
k_attn(const float* __restrict__ coords,
       const float* __restrict__ Wd1, const float* __restrict__ bd1,
       const float* __restrict__ Wd2, const float* __restrict__ bd2)
{
    extern __shared__ float smp[];
    float* Qs   = smp;                    // [112][132] transposed
    float* Ks   = Qs + 112 * QS_LD;       // [112][68]  transposed
    float* Vs0  = Ks + 112 * KS_LD;       // [2][64][116] natural, double buffered
    float* Ps   = Vs0 + 2 * 64 * VS_LD;   // [64][130]  key-major
    float* cqx  = Ps + 64 * PS_LD;
    float* cqy  = cqx + FBM;
    float* cqz  = cqy + FBM;
    float* qn2s = cqz + FBM;
    float* ckx  = qn2s + FBM;
    float* cky  = ckx + FBK;
    float* ckz  = cky + FBK;
    float* kn2s = ckz + FBK;
    float* kn   = kn2s + FBK;             // [64] knot table
    float* al   = kn + 64;                // [33]
    float* be   = al + 33;                // [33]

    const int bh = blockIdx.y;
    const int b  = bh >> 3, h = bh & 7;
    const int rb = blockIdx.x * FBM;
    const int tid = threadIdx.x;
    const int tm = tid >> 4, tn = tid & 15;   // 32 x 16
    const int m0 = tm * 4, n0s = tn * 4, n0o = tn * 7;

    const float* Qg = g_Qc + (size_t)bh * NS * NCD;
    const float* Kg = g_Kc + (size_t)bh * NS * NCD;
    const float* Vg = g_Vc + (size_t)bh * NS * NCD;

    const int lKey[4] = { (tid) / 28, (tid + 512) / 28, (tid + 1024) / 28, (tid + 1536) / 28 };
    const int lC4[4]  = { ((tid) % 28) * 4, ((tid + 512) % 28) * 4,
                          ((tid + 1024) % 28) * 4, ((tid + 1536) % 28) * 4 };
    const bool lOk3 = (tid + 1536) < 1792;

    if (tid == 0) {
        float kj[32], da_[32], db_[32];
        int m = 0;
        float a0 = 0.f, b0 = bd2[h];
        for (int j = 0; j < 32; j++) {
            float w = Wd1[j], c = bd1[j], u = Wd2[j * 8 + h];
            if (w > 0.f) {
                float kk = -c / w;
                if (kk <= 0.f) { a0 += w * u; b0 += c * u; }
                else if (kk < 15.f) { kj[m] = kk; da_[m] = w * u; db_[m] = c * u; m++; }
            } else if (w < 0.f) {
                float kk = -c / w;
                if (kk >= 15.f) { a0 += w * u; b0 += c * u; }
                else if (kk > 0.f) {
                    a0 += w * u; b0 += c * u;
                    kj[m] = kk; da_[m] = -w * u; db_[m] = -c * u; m++;
                }
            } else if (c > 0.f) { b0 += c * u; }
        }
        for (int i = 1; i < m; i++) {
            float kv = kj[i], av = da_[i], bv = db_[i]; int p = i - 1;
            while (p >= 0 && kj[p] > kv) {
                kj[p + 1] = kj[p]; da_[p + 1] = da_[p]; db_[p + 1] = db_[p]; p--;
            }
            kj[p + 1] = kv; da_[p + 1] = av; db_[p + 1] = bv;
        }
        kn[0] = -1e30f; al[0] = a0; be[0] = b0;
        for (int i = 0; i < m; i++) {
            kn[i + 1] = kj[i];
            al[i + 1] = al[i] + da_[i];
            be[i + 1] = be[i] + db_[i];
        }
        for (int i = m + 1; i < 64; i++) kn[i] = 1e30f;
    }

#pragma unroll
    for (int t = 0; t < 7; t++) {
        int idx = tid + t * 512;
        int m = idx / 28, c4 = (idx % 28) * 4;
        float4 v = *(const float4*)(Qg + (size_t)(rb + m) * NCD + c4);
        Qs[(c4 + 0) * QS_LD + m] = v.x;
        Qs[(c4 + 1) * QS_LD + m] = v.y;
        Qs[(c4 + 2) * QS_LD + m] = v.z;
        Qs[(c4 + 3) * QS_LD + m] = v.w;
    }
    if (tid < FBM) {
        int q = rb + tid;
        cqx[tid] = coords[((size_t)b * NS + q) * 3 + 0];
        cqy[tid] = coords[((size_t)b * NS + q) * 3 + 1];
        cqz[tid] = coords[((size_t)b * NS + q) * 3 + 2];
        qn2s[tid] = g_qn2[bh * NS + q];
    }

    float4 kreg[4];
    float crx = 0.f, cry = 0.f, crz = 0.f, crn = 0.f;
#pragma unroll
    for (int t = 0; t < 4; t++) {
        if (t < 3 || lOk3) {
            kreg[t] = *(const float4*)(Kg + (size_t)lKey[t] * NCD + lC4[t]);
            uint32_t dst = (uint32_t)__cvta_generic_to_shared(Vs0 + lKey[t] * VS_LD + lC4[t]);
            cpasync16(dst, Vg + (size_t)lKey[t] * NCD + lC4[t]);
        }
    }
    CP_COMMIT();
    if (tid < FBK) {
        crx = coords[((size_t)b * NS + tid) * 3 + 0];
        cry = coords[((size_t)b * NS + tid) * 3 + 1];
        crz = coords[((size_t)b * NS + tid) * 3 + 2];
        crn = g_kn2[bh * NS + tid];
    }

    unsigned long long accO[2][7];
#pragma unroll
    for (int t = 0; t < 2; t++)
#pragma unroll
        for (int c = 0; c < 7; c++) accO[t][c] = 0ull;
    float run_m[4], run_s[4];
#pragma unroll
    for (int i = 0; i < 4; i++) { run_m[i] = -1e30f; run_s[i] = 0.f; }

    int buf = 0;
    for (int kb = 0; kb < NS; kb += FBK) {
#pragma unroll
        for (int t = 0; t < 4; t++) {
            if (t < 3 || lOk3) {
                int key = lKey[t], c4 = lC4[t];
                Ks[(c4 + 0) * KS_LD + key] = kreg[t].x;
                Ks[(c4 + 1) * KS_LD + key] = kreg[t].y;
                Ks[(c4 + 2) * KS_LD + key] = kreg[t].z;
                Ks[(c4 + 3) * KS_LD + key] = kreg[t].w;
            }
        }
        if (tid < FBK) { ckx[tid] = crx; cky[tid] = cry; ckz[tid] = crz; kn2s[tid] = crn; }
        __syncthreads();

        unsigned long long accS[2][4];
#pragma unroll
        for (int t = 0; t < 2; t++)
#pragma unroll
            for (int j = 0; j < 4; j++) accS[t][j] = 0ull;
#pragma unroll 4
        for (int d = 0; d < NCD; d++) {
            float4 qv = *(const float4*)(Qs + d * QS_LD + m0);
            float4 kv = *(const float4*)(Ks + d * KS_LD + n0s);
            unsigned long long a0 = pack2(qv.x, qv.y), a1 = pack2(qv.z, qv.w);
            unsigned long long b0 = dup2(kv.x), b1 = dup2(kv.y), b2 = dup2(kv.z), b3 = dup2(kv.w);
            ffma2(accS[0][0], a0, b0); ffma2(accS[0][1], a0, b1);
            ffma2(accS[0][2], a0, b2); ffma2(accS[0][3], a0, b3);
            ffma2(accS[1][0], a1, b0); ffma2(accS[1][1], a1, b1);
            ffma2(accS[1][2], a1, b2); ffma2(accS[1][3], a1, b3);
        }

        const int kb2 = kb + FBK;
        if (kb2 < NS) {
            float* Vnext = Vs0 + (buf ^ 1) * 64 * VS_LD;
#pragma unroll
            for (int t = 0; t < 4; t++) {
                if (t < 3 || lOk3) {
                    kreg[t] = *(const float4*)(Kg + (size_t)(kb2 + lKey[t]) * NCD + lC4[t]);
                    uint32_t dst = (uint32_t)__cvta_generic_to_shared(Vnext + lKey[t] * VS_LD + lC4[t]);
                    cpasync16(dst, Vg + (size_t)(kb2 + lKey[t]) * NCD + lC4[t]);
                }
            }
            if (tid < FBK) {
                crx = coords[((size_t)b * NS + kb2 + tid) * 3 + 0];
                cry = coords[((size_t)b * NS + kb2 + tid) * 3 + 1];
                crz = coords[((size_t)b * NS + kb2 + tid) * 3 + 2];
                crn = g_kn2[bh * NS + kb2 + tid];
            }
        }
        CP_COMMIT();

        float Sv[4][4];
#pragma unroll
        for (int t = 0; t < 2; t++)
#pragma unroll
            for (int j = 0; j < 4; j++) unpk(accS[t][j], Sv[2 * t][j], Sv[2 * t + 1][j]);

#pragma unroll
        for (int i = 0; i < 4; i++) {
            float qx = cqx[m0 + i], qy = cqy[m0 + i], qz = cqz[m0 + i];
            float qn = qn2s[m0 + i];
#pragma unroll
            for (int j = 0; j < 4; j++) {
                int gk = n0s + j;
                float dx = qx - ckx[gk], dy = qy - cky[gk], dz = qz - ckz[gk];
                float d2 = fmaf(dx, dx, fmaf(dy, dy, dz * dz));
                float d = sqrtf(d2);
                int idx = 0;
#pragma unroll
                for (int st = 32; st > 0; st >>= 1)
                    if (kn[idx + st] <= d) idx += st;
                float bias = fmaf(al[idx], d, be[idx]) - 0.5f * (qn + kn2s[gk]);
                Sv[i][j] = (d2 < 225.f) ? Sv[i][j] + bias : -1e9f;
            }
        }

        float scl[4];
#pragma unroll
        for (int i = 0; i < 4; i++) {
            float mx = fmaxf(fmaxf(Sv[i][0], Sv[i][1]), fmaxf(Sv[i][2], Sv[i][3]));
#pragma unroll
            for (int o = 8; o > 0; o >>= 1) mx = fmaxf(mx, __shfl_xor_sync(0xffffffffu, mx, o));
            float nm = fmaxf(run_m[i], mx);
            float sc = __expf(run_m[i] - nm);
            float ts = 0.f;
#pragma unroll
            for (int j = 0; j < 4; j++) { float p = __expf(Sv[i][j] - nm); Sv[i][j] = p; ts += p; }
            run_s[i] = run_s[i] * sc + ts;
            run_m[i] = nm;
            scl[i] = sc;
        }
        {
            unsigned long long s0 = pack2(scl[0], scl[1]);
            unsigned long long s1 = pack2(scl[2], scl[3]);
#pragma unroll
            for (int c = 0; c < 7; c++) { mul2(accO[0][c], s0); mul2(accO[1][c], s1); }
        }

#pragma unroll
        for (int j = 0; j < 4; j++) {
            float* pp = Ps + (n0s + j) * PS_LD + m0;
            pp[0] = Sv[0][j]; pp[1] = Sv[1][j]; pp[2] = Sv[2][j]; pp[3] = Sv[3][j];
        }
        CP_WAIT1();
        __syncthreads();

        const float* Vs = Vs0 + buf * 64 * VS_LD;
#pragma unroll 2
        for (int kk = 0; kk < FBK; kk++) {
            const float* pr = Ps + kk * PS_LD + m0;
            const float* vr = Vs + kk * VS_LD + n0o;
            unsigned long long a0 = *(const unsigned long long*)(pr);
            unsigned long long a1 = *(const unsigned long long*)(pr + 2);
#pragma unroll
            for (int c = 0; c < 7; c++) {
                unsigned long long bd = dup2(vr[c]);
                ffma2(accO[0][c], a0, bd);
                ffma2(accO[1][c], a1, bd);
            }
        }
        buf ^= 1;
    }

    float fac[4];
#pragma unroll
    for (int i = 0; i < 4; i++) {
        float s = run_s[i];
#pragma unroll
        for (int o = 8; o > 0; o >>= 1) s += __shfl_xor_sync(0xffffffffu, s, o);
        fac[i] = 1.0f / s;
    }
#pragma unroll
    for (int t = 0; t < 2; t++) {
        int q0 = rb + m0 + 2 * t;
        size_t base0 = (size_t)(b * NS + q0) * ATT_W;
        size_t base1 = base0 + ATT_W;
#pragma unroll
        for (int c = 0; c < 7; c++) {
            int col = n0o + c;
            int cc = (col < 64) ? (h * 64 + col) : (512 + h * 48 + (col - 64));
            float o0, o1; unpk(accO[t][c], o0, o1);
            g_att[base0 + cc] = o0 * fac[2 * t];
            g_att[base1 + cc] = o1 * fac[2 * t + 1];
        }
    }
}

// ---------------- Coords update (block per row) ----------------
__global__ void k_coords(const float* __restrict__ coords, float* __restrict__ outc) {
    int row = blockIdx.x, t = threadIdx.x;   // 128 threads
    const float* ap = g_att + (size_t)row * ATT_W + 512;
    __shared__ float sx[128], sy[128], sz[128];
    sx[t] = ap[t * 3 + 0]; sy[t] = ap[t * 3 + 1]; sz[t] = ap[t * 3 + 2];
    __syncthreads();
    for (int s = 64; s > 0; s >>= 1) {
        if (t < s) { sx[t] += sx[t + s]; sy[t] += sy[t + s]; sz[t] += sz[t + s]; }
        __syncthreads();
    }
    if (t == 0) {
        outc[row * 3 + 0] = coords[row * 3 + 0] + sx[0] * (0.1f / 128.f);
        outc[row * 3 + 1] = coords[row * 3 + 1] + sy[0] * (0.1f / 128.f);
        outc[row * 3 + 2] = coords[row * 3 + 2] + sz[0] * (0.1f / 128.f);
    }
}

// ---------------- Launch ----------------
extern "C" void kernel_launch(void* const* d_in, const int* in_sizes, int n_in,
                              void* d_out, int out_size) {
    const float* x      = (const float*)d_in[0];
    const float* coords = (const float*)d_in[1];
    const float* Wq     = (const float*)d_in[2];
    const float* Wk     = (const float*)d_in[3];
    const float* Wv     = (const float*)d_in[4];
    const float* Wqp    = (const float*)d_in[5];
    const float* bqp    = (const float*)d_in[6];
    const float* Wkp    = (const float*)d_in[7];
    const float* bkp    = (const float*)d_in[8];
    const float* Wvp    = (const float*)d_in[9];
    const float* bvp    = (const float*)d_in[10];
    const float* Wd1    = (const float*)d_in[11];
    const float* bd1    = (const float*)d_in[12];
    const float* Wd2    = (const float*)d_in[13];
    const float* bd2    = (const float*)d_in[14];
    const float* Wo     = (const float*)d_in[15];
    const float* bo     = (const float*)d_in[16];
    const float* g1     = (const float*)d_in[17];
    const float* b1     = (const float*)d_in[18];
    const float* g2     = (const float*)d_in[19];
    const float* b2     = (const float*)d_in[20];
    float* out = (float*)d_out;

    float *p_xn, *p_att, *p_pre;
    cudaGetSymbolAddress((void**)&p_xn,  g_xn);
    cudaGetSymbolAddress((void**)&p_att, g_att);
    cudaGetSymbolAddress((void**)&p_pre, g_pre);

    const int smem_attn = (112 * QS_LD + 112 * KS_LD + 2 * 64 * VS_LD + 64 * PS_LD +
                           4 * FBM + 4 * FBK + 64 + 33 + 33) * sizeof(float);
    cudaFuncSetAttribute(k_attn, cudaFuncAttributeMaxDynamicSharedMemorySize, smem_attn);

    // 1. LayerNorm
    k_ln<<<NROWS, 256>>>(x, nullptr, g1, b1, p_xn);
    // 2. Projection GEMM v3: 64x64 tiles, occ 4, 1344 CTAs
    k_proj<<<dim3(NCAT / 64, NROWS / 64), 256>>>(coords, Wq, Wk, Wv, Wqp, Wkp, Wvp,
                                                 bqp, bkp, bvp);
    // 3. Point norms
    k_norms<<<NBH * NS / 8, 256>>>();
    // 4. Fused attention (exact R6 pipeline)
    k_attn<<<dim3(NS / FBM, NBH), 512, smem_attn>>>(coords, Wd1, bd1, Wd2, bd2);
    // 5. Output projection: 64x64 tiles, 256 CTAs, occ 4
    gemm_out<<<dim3(ND / 64, NROWS / 64), 256>>>(p_att, Wo, bo, p_pre);
    // 6. Residual + final LayerNorm -> out
    k_ln<<<NROWS, 256>>>(x, p_pre, g2, b2, out);
    // 7. Coords update -> second output
    k_coords<<<NROWS, 128>>>(coords, out + (size_t)NROWS * ND);
}

// round 16
// speedup vs baseline: 1.1537x; 1.1537x over previous
#include <cuda_runtime.h>
#include <cuda_fp16.h>
#include <math.h>
#include <stdint.h>

#define NB 2
#define NS 1024
#define ND 512
#define NH 8
#define NCAT 2688
#define NCD 112
#define NBH 16
#define NROWS 2048
#define ATT_W 896

#define FBM 128
#define FBK 64
#define VS_LD 116
#define PS_LD 132
#define QK_LD 120

__device__ float g_xn[NROWS * ND];
__device__ __half g_Qh[NBH * NS * NCD];
__device__ __half g_Ql[NBH * NS * NCD];
__device__ __half g_Kh[NBH * NS * NCD];
__device__ __half g_Kl[NBH * NS * NCD];
__device__ float g_Vc[NBH * NS * NCD];
__device__ float g_qn2[NBH * NS];
__device__ float g_kn2[NBH * NS];
__device__ float g_att[NROWS * ATT_W];
__device__ float g_pre[NROWS * ND];

__device__ __forceinline__ unsigned long long dup2(float x) {
    unsigned long long r; unsigned u = __float_as_uint(x);
    asm("mov.b64 %0, {%1, %1};" : "=l"(r) : "r"(u));
    return r;
}
__device__ __forceinline__ unsigned long long pack2(float lo, float hi) {
    unsigned long long r;
    asm("mov.b64 %0, {%1, %2};" : "=l"(r) : "r"(__float_as_uint(lo)), "r"(__float_as_uint(hi)));
    return r;
}
__device__ __forceinline__ void ffma2(unsigned long long& c, unsigned long long a, unsigned long long b) {
    asm("fma.rn.f32x2 %0, %1, %2, %0;" : "+l"(c) : "l"(a), "l"(b));
}
__device__ __forceinline__ void mul2(unsigned long long& c, unsigned long long a) {
    asm("mul.rn.f32x2 %0, %0, %1;" : "+l"(c) : "l"(a));
}
__device__ __forceinline__ void unpk(unsigned long long v, float& lo, float& hi) {
    unsigned a, b;
    asm("mov.b64 {%0, %1}, %2;" : "=r"(a), "=r"(b) : "l"(v));
    lo = __uint_as_float(a); hi = __uint_as_float(b);
}
__device__ __forceinline__ void cpasync16(uint32_t dst, const void* src) {
    asm volatile("cp.async.cg.shared.global [%0], [%1], 16;" :: "r"(dst), "l"(src));
}
#define CP_COMMIT() asm volatile("cp.async.commit_group;")
#define CP_WAIT1()  asm volatile("cp.async.wait_group 1;")

__device__ __forceinline__ uint32_t smaddr(const void* p) {
    return (uint32_t)__cvta_generic_to_shared(p);
}
__device__ __forceinline__ void ldm_x4(uint32_t a, uint32_t& r0, uint32_t& r1, uint32_t& r2, uint32_t& r3) {
    asm volatile("ldmatrix.sync.aligned.m8n8.x4.shared.b16 {%0,%1,%2,%3}, [%4];"
                 : "=r"(r0), "=r"(r1), "=r"(r2), "=r"(r3) : "r"(a));
}
__device__ __forceinline__ void ldm_x2(uint32_t a, uint32_t& r0, uint32_t& r1) {
    asm volatile("ldmatrix.sync.aligned.m8n8.x2.shared.b16 {%0,%1}, [%2];"
                 : "=r"(r0), "=r"(r1) : "r"(a));
}
__device__ __forceinline__ void mma16816(float* c, uint32_t a0, uint32_t a1, uint32_t a2, uint32_t a3,
                                         uint32_t b0, uint32_t b1) {
    asm volatile("mma.sync.aligned.m16n8k16.row.col.f32.f16.f16.f32 "
                 "{%0,%1,%2,%3}, {%4,%5,%6,%7}, {%8,%9}, {%0,%1,%2,%3};"
                 : "+f"(c[0]), "+f"(c[1]), "+f"(c[2]), "+f"(c[3])
                 : "r"(a0), "r"(a1), "r"(a2), "r"(a3), "r"(b0), "r"(b1));
}

// ---------------- LayerNorm ----------------
__global__ void k_ln(const float* __restrict__ x, const float* __restrict__ res,
                     const float* __restrict__ g, const float* __restrict__ b,
                     float* __restrict__ y) {
    int row = blockIdx.x, tid = threadIdx.x;
    const float* xr = x + (size_t)row * ND;
    float v0 = xr[tid], v1 = xr[tid + 256];
    if (res) {
        v0 += res[(size_t)row * ND + tid];
        v1 += res[(size_t)row * ND + tid + 256];
    }
    __shared__ float ws[8], ws2[8];
    float s = v0 + v1;
#pragma unroll
    for (int o = 16; o > 0; o >>= 1) s += __shfl_xor_sync(0xffffffffu, s, o);
    if ((tid & 31) == 0) ws[tid >> 5] = s;
    __syncthreads();
    float tot = ws[0] + ws[1] + ws[2] + ws[3] + ws[4] + ws[5] + ws[6] + ws[7];
    float mean = tot * (1.0f / ND);
    float d0 = v0 - mean, d1 = v1 - mean;
    float s2 = d0 * d0 + d1 * d1;
#pragma unroll
    for (int o = 16; o > 0; o >>= 1) s2 += __shfl_xor_sync(0xffffffffu, s2, o);
    if ((tid & 31) == 0) ws2[tid >> 5] = s2;
    __syncthreads();
    float tv = ws2[0] + ws2[1] + ws2[2] + ws2[3] + ws2[4] + ws2[5] + ws2[6] + ws2[7];
    float rstd = rsqrtf(tv * (1.0f / ND) + 1e-5f);
    float* yr = y + (size_t)row * ND;
    yr[tid]       = d0 * rstd * g[tid] + b[tid];
    yr[tid + 256] = d1 * rstd * g[tid + 256] + b[tid + 256];
}

// ---------------- hi/lo split store ----------------
__device__ __forceinline__ void store_qk(__half* H, __half* L, size_t o, float lo, float hi) {
    __half h0 = __float2half_rn(lo);
    __half l0 = __float2half_rn(lo - __half2float(h0));
    __half h1 = __float2half_rn(hi);
    __half l1 = __float2half_rn(hi - __half2float(h1));
    *(__half2*)(H + o) = __halves2half2(h0, h1);
    *(__half2*)(L + o) = __halves2half2(l0, l1);
}

__device__ __forceinline__ void scatter_proj2(
    int b, int s, int r, int c, float lo, float hi, const float* __restrict__ coords,
    const float* __restrict__ bqp, const float* __restrict__ bkp, const float* __restrict__ bvp)
{
    if (c < 1536) {
        int seg = c >> 9;
        int cc = c & 511;
        int hh = cc >> 6, j = cc & 63;
        size_t o = ((size_t)(b * NH + hh) * NS + s) * NCD + j;
        if (seg == 0) { lo *= 0.125f; hi *= 0.125f;
            store_qk(g_Qh, g_Ql, o, lo, hi);
        } else if (seg == 1) {
            store_qk(g_Kh, g_Kl, o, lo, hi);
        } else {
            *(unsigned long long*)(g_Vc + o) = pack2(lo, hi);
        }
    } else {
        int t = c - 1536;
        int seg = t / 384;
        int cc = t - seg * 384;
        int hh = cc / 48, jj = cc - hh * 48;
        size_t o = ((size_t)(b * NH + hh) * NS + s) * NCD + 64 + jj;
        if (seg == 0) {
            lo += bqp[cc]     + coords[r * 3 + (jj % 3)];
            hi += bqp[cc + 1] + coords[r * 3 + ((jj + 1) % 3)];
            store_qk(g_Qh, g_Ql, o, lo, hi);
        } else if (seg == 1) {
            lo += bkp[cc]     + coords[r * 3 + (jj % 3)];
            hi += bkp[cc + 1] + coords[r * 3 + ((jj + 1) % 3)];
            store_qk(g_Kh, g_Kl, o, lo, hi);
        } else {
            lo += bvp[cc];
            hi += bvp[cc + 1];
            *(unsigned long long*)(g_Vc + o) = pack2(lo, hi);
        }
    }
}

// ---------------- Projection GEMM: 64x64 tiles, occ 4 ----------------
__global__ void __launch_bounds__(256, 4)
k_proj(const float* __restrict__ coords,
       const float* __restrict__ Wq, const float* __restrict__ Wk, const float* __restrict__ Wv,
       const float* __restrict__ Wqp, const float* __restrict__ Wkp, const float* __restrict__ Wvp,
       const float* __restrict__ bqp, const float* __restrict__ bkp, const float* __restrict__ bvp)
{
    const float* A = g_xn;
    __shared__ float As[2][16][68];
    __shared__ float Bs[2][16][64];
    const int tid = threadIdx.x;
    const int tn = tid & 15, tm = tid >> 4;
    const int m0 = tm * 4, n0 = tn * 4;
    const int rb = blockIdx.y * 64, cb = blockIdx.x * 64;

    const float* W; int ldw, coff;
    if      (cb < 512)  { W = Wq;  ldw = 512; coff = cb; }
    else if (cb < 1024) { W = Wk;  ldw = 512; coff = cb - 512; }
    else if (cb < 1536) { W = Wv;  ldw = 512; coff = cb - 1024; }
    else if (cb < 1920) { W = Wqp; ldw = 384; coff = cb - 1536; }
    else if (cb < 2304) { W = Wkp; ldw = 384; coff = cb - 1920; }
    else                { W = Wvp; ldw = 384; coff = cb - 2304; }

    unsigned long long acc[4][2];
#pragma unroll
    for (int i = 0; i < 4; i++) { acc[i][0] = 0ull; acc[i][1] = 0ull; }

    const int aR = tid >> 2, aC = (tid & 3) * 4;
    const int bR = tid >> 4, bC = (tid & 15) * 4;

    float4 av, bv;
    av = *(const float4*)(A + (size_t)(rb + aR) * ND + aC);
    bv = *(const float4*)(W + (size_t)bR * ldw + coff + bC);
    As[0][aC + 0][aR] = av.x; As[0][aC + 1][aR] = av.y;
    As[0][aC + 2][aR] = av.z; As[0][aC + 3][aR] = av.w;
    *(float4*)&Bs[0][bR][bC] = bv;
    __syncthreads();

    int buf = 0;
    for (int k0 = 0; k0 < ND; k0 += 16) {
        const bool nxt = (k0 + 16) < ND;
        if (nxt) {
            av = *(const float4*)(A + (size_t)(rb + aR) * ND + k0 + 16 + aC);
            bv = *(const float4*)(W + (size_t)(k0 + 16 + bR) * ldw + coff + bC);
        }
#pragma unroll
        for (int kk = 0; kk < 16; kk++) {
            unsigned long long bb0 = *(const unsigned long long*)&Bs[buf][kk][n0];
            unsigned long long bb1 = *(const unsigned long long*)&Bs[buf][kk][n0 + 2];
#pragma unroll
            for (int i = 0; i < 4; i++) {
                unsigned long long ad = dup2(As[buf][kk][m0 + i]);
                ffma2(acc[i][0], ad, bb0);
                ffma2(acc[i][1], ad, bb1);
            }
        }
        if (nxt) {
            int nb = buf ^ 1;
            As[nb][aC + 0][aR] = av.x; As[nb][aC + 1][aR] = av.y;
            As[nb][aC + 2][aR] = av.z; As[nb][aC + 3][aR] = av.w;
            *(float4*)&Bs[nb][bR][bC] = bv;
            __syncthreads();
            buf = nb;
        }
    }

#pragma unroll
    for (int i = 0; i < 4; i++) {
        int r = rb + m0 + i;
        int b = r >> 10, s = r & 1023;
        float l0, h0, l1, h1;
        unpk(acc[i][0], l0, h0); unpk(acc[i][1], l1, h1);
        scatter_proj2(b, s, r, cb + n0,     l0, h0, coords, bqp, bkp, bvp);
        scatter_proj2(b, s, r, cb + n0 + 2, l1, h1, coords, bqp, bkp, bvp);
    }
}

// ---------------- Output projection GEMM ----------------
__global__ void __launch_bounds__(256, 4)
gemm_out(const float* __restrict__ A, const float* __restrict__ B,
         const float* __restrict__ bias, float* __restrict__ C)
{
    const int N = ND, K = ATT_W;
    __shared__ float As[2][16][68];
    __shared__ float Bs[2][16][64];
    const int tid = threadIdx.x;
    const int tn = tid & 15, tm = tid >> 4;
    const int m0 = tm * 4, n0 = tn * 4;
    const int rb = blockIdx.y * 64, cb = blockIdx.x * 64;

    unsigned long long acc[4][2];
#pragma unroll
    for (int i = 0; i < 4; i++) { acc[i][0] = 0ull; acc[i][1] = 0ull; }

    const int aR = tid >> 2, aC = (tid & 3) * 4;
    const int bR = tid >> 4, bC = (tid & 15) * 4;

    float4 av, bv;
    av = *(const float4*)(A + (size_t)(rb + aR) * K + aC);
    bv = *(const float4*)(B + (size_t)bR * N + cb + bC);
    As[0][aC + 0][aR] = av.x; As[0][aC + 1][aR] = av.y;
    As[0][aC + 2][aR] = av.z; As[0][aC + 3][aR] = av.w;
    *(float4*)&Bs[0][bR][bC] = bv;
    __syncthreads();

    int buf = 0;
    for (int k0 = 0; k0 < K; k0 += 16) {
        const bool nxt = (k0 + 16) < K;
        if (nxt) {
            av = *(const float4*)(A + (size_t)(rb + aR) * K + k0 + 16 + aC);
            bv = *(const float4*)(B + (size_t)(k0 + 16 + bR) * N + cb + bC);
        }
#pragma unroll
        for (int kk = 0; kk < 16; kk++) {
            unsigned long long bb0 = *(const unsigned long long*)&Bs[buf][kk][n0];
            unsigned long long bb1 = *(const unsigned long long*)&Bs[buf][kk][n0 + 2];
#pragma unroll
            for (int i = 0; i < 4; i++) {
                unsigned long long ad = dup2(As[buf][kk][m0 + i]);
                ffma2(acc[i][0], ad, bb0);
                ffma2(acc[i][1], ad, bb1);
            }
        }
        if (nxt) {
            int nb = buf ^ 1;
            As[nb][aC + 0][aR] = av.x; As[nb][aC + 1][aR] = av.y;
            As[nb][aC + 2][aR] = av.z; As[nb][aC + 3][aR] = av.w;
            *(float4*)&Bs[nb][bR][bC] = bv;
            __syncthreads();
            buf = nb;
        }
    }

#pragma unroll
    for (int i = 0; i < 4; i++) {
        int r = rb + m0 + i;
        int c = cb + n0;
        float l0, h0, l1, h1;
        unpk(acc[i][0], l0, h0); unpk(acc[i][1], l1, h1);
        l0 += bias[c];     h0 += bias[c + 1];
        l1 += bias[c + 2]; h1 += bias[c + 3];
        *(unsigned long long*)(C + (size_t)r * N + c)     = pack2(l0, h0);
        *(unsigned long long*)(C + (size_t)r * N + c + 2) = pack2(l1, h1);
    }
}

// ---------------- Point norms (reconstructed hi+lo) ----------------
__global__ void k_norms() {
    int t = threadIdx.x;
    int r = blockIdx.x * 8 + (t >> 5);
    int lane = t & 31;
    size_t base = (size_t)r * NCD + 64;
    float qa = __half2float(g_Qh[base + lane]) + __half2float(g_Ql[base + lane]);
    float ka = __half2float(g_Kh[base + lane]) + __half2float(g_Kl[base + lane]);
    float qb = 0.f, kb = 0.f;
    if (lane < 16) {
        qb = __half2float(g_Qh[base + 32 + lane]) + __half2float(g_Ql[base + 32 + lane]);
        kb = __half2float(g_Kh[base + 32 + lane]) + __half2float(g_Kl[base + 32 + lane]);
    }
    float qs = qa * qa + qb * qb;
    float ks = ka * ka + kb * kb;
#pragma unroll
    for (int o = 16; o > 0; o >>= 1) {
        qs += __shfl_xor_sync(0xffffffffu, qs, o);
        ks += __shfl_xor_sync(0xffffffffu, ks, o);
    }
    if (lane == 0) { g_qn2[r] = qs; g_kn2[r] = ks; }
}

// ---------------- Fused attention v16: HMMA S-loop (4-term hi/lo), FFMA2 PV ------------
__global__ void __launch_bounds__(256, 1)
k_attn(const float* __restrict__ coords,
       const float* __restrict__ Wd1, const float* __restrict__ bd1,
       const float* __restrict__ Wd2, const float* __restrict__ bd2)
{
    extern __shared__ char sraw[];
    __half* Qh = (__half*)sraw;                 // [128][120]
    __half* Ql = Qh + 128 * QK_LD;
    __half* Kh = Ql + 128 * QK_LD;              // [64][120]
    __half* Kl = Kh + 64 * QK_LD;
    float* Vs0 = (float*)(Kl + 64 * QK_LD);     // [2][64][116]
    float* Ps  = Vs0 + 2 * 64 * VS_LD;          // [64][132]
    float* cqx = Ps + 64 * PS_LD;
    float* cqy = cqx + FBM;
    float* cqz = cqy + FBM;
    float* qn2s = cqz + FBM;
    float* ckx = qn2s + FBM;
    float* cky = ckx + FBK;
    float* ckz = cky + FBK;
    float* kn2s = ckz + FBK;
    float* kn = kn2s + FBK;                     // [64]
    float* al = kn + 64;                        // [33]
    float* be = al + 33;                        // [33]
    float* rowsc = be + 33;                     // [128]

    const int bh = blockIdx.y;
    const int b = bh >> 3, h = bh & 7;
    const int rb = blockIdx.x * FBM;
    const int tid = threadIdx.x;
    const int lane = tid & 31, mb = tid >> 5;

    const __half* QhG = g_Qh + (size_t)bh * NS * NCD;
    const __half* QlG = g_Ql + (size_t)bh * NS * NCD;
    const __half* KhG = g_Kh + (size_t)bh * NS * NCD;
    const __half* KlG = g_Kl + (size_t)bh * NS * NCD;
    const float*  Vg  = g_Vc + (size_t)bh * NS * NCD;

    if (tid == 0) {
        float kj[32], da_[32], db_[32];
        int m = 0;
        float a0 = 0.f, b0 = bd2[h];
        for (int j = 0; j < 32; j++) {
            float w = Wd1[j], c = bd1[j], u = Wd2[j * 8 + h];
            if (w > 0.f) {
                float kk = -c / w;
                if (kk <= 0.f) { a0 += w * u; b0 += c * u; }
                else if (kk < 15.f) { kj[m] = kk; da_[m] = w * u; db_[m] = c * u; m++; }
            } else if (w < 0.f) {
                float kk = -c / w;
                if (kk >= 15.f) { a0 += w * u; b0 += c * u; }
                else if (kk > 0.f) {
                    a0 += w * u; b0 += c * u;
                    kj[m] = kk; da_[m] = -w * u; db_[m] = -c * u; m++;
                }
            } else if (c > 0.f) { b0 += c * u; }
        }
        for (int i = 1; i < m; i++) {
            float kv = kj[i], av = da_[i], bv = db_[i]; int p = i - 1;
            while (p >= 0 && kj[p] > kv) {
                kj[p + 1] = kj[p]; da_[p + 1] = da_[p]; db_[p + 1] = db_[p]; p--;
            }
            kj[p + 1] = kv; da_[p + 1] = av; db_[p + 1] = bv;
        }
        kn[0] = -1e30f; al[0] = a0; be[0] = b0;
        for (int i = 0; i < m; i++) {
            kn[i + 1] = kj[i];
            al[i + 1] = al[i] + da_[i];
            be[i + 1] = be[i] + db_[i];
        }
        for (int i = m + 1; i < 64; i++) kn[i] = 1e30f;
    }

    // Q strip (hi/lo), 1792 uint4 each, 7/thread
#pragma unroll
    for (int t = 0; t < 7; t++) {
        int idx = tid + t * 256;
        int m = idx / 14, c8 = (idx % 14) * 8;
        *(uint4*)(Qh + m * QK_LD + c8) = *(const uint4*)(QhG + (size_t)(rb + m) * NCD + c8);
        *(uint4*)(Ql + m * QK_LD + c8) = *(const uint4*)(QlG + (size_t)(rb + m) * NCD + c8);
    }
    if (tid < FBM) {
        int q = rb + tid;
        cqx[tid] = coords[((size_t)b * NS + q) * 3 + 0];
        cqy[tid] = coords[((size_t)b * NS + q) * 3 + 1];
        cqz[tid] = coords[((size_t)b * NS + q) * 3 + 2];
        qn2s[tid] = g_qn2[bh * NS + q];
    }

    // Loader geometry: K 896 uint4 (guarded 4/thread); V 1792 float4 (7/thread)
    int kM[4], kC[4]; bool kOk[4];
#pragma unroll
    for (int t = 0; t < 4; t++) {
        int idx = tid + t * 256;
        kOk[t] = idx < 896; int ix = kOk[t] ? idx : 0;
        kM[t] = ix / 14; kC[t] = (ix % 14) * 8;
    }
    int lKey[7], lC4[7];
#pragma unroll
    for (int t = 0; t < 7; t++) { int idx = tid + t * 256; lKey[t] = idx / 28; lC4[t] = (idx % 28) * 4; }

    uint4 kregH[4], kregL[4];
    float crx = 0.f, cry = 0.f, crz = 0.f, crn = 0.f;
#pragma unroll
    for (int t = 0; t < 4; t++) {
        if (kOk[t]) {
            kregH[t] = *(const uint4*)(KhG + (size_t)kM[t] * NCD + kC[t]);
            kregL[t] = *(const uint4*)(KlG + (size_t)kM[t] * NCD + kC[t]);
        }
    }
#pragma unroll
    for (int t = 0; t < 7; t++)
        cpasync16(smaddr(Vs0 + lKey[t] * VS_LD + lC4[t]), Vg + (size_t)lKey[t] * NCD + lC4[t]);
    CP_COMMIT();
    if (tid < FBK) {
        crx = coords[((size_t)b * NS + tid) * 3 + 0];
        cry = coords[((size_t)b * NS + tid) * 3 + 1];
        crz = coords[((size_t)b * NS + tid) * 3 + 2];
        crn = g_kn2[bh * NS + tid];
    }

    // ldmatrix addresses
    const int arow = mb * 16 + (lane & 15);
    const uint32_t aoff = (uint32_t)((arow * QK_LD + ((lane >> 4) << 3)) * 2);
    const int l2 = lane & 15;
    const uint32_t boff = (uint32_t)((((l2 & 7)) * QK_LD + (((l2 >> 3) & 1) << 3)) * 2);
    const uint32_t qh_a = smaddr(Qh) + aoff;
    const uint32_t ql_a = smaddr(Ql) + aoff;
    const uint32_t kh_b = smaddr(Kh) + boff;
    const uint32_t kl_b = smaddr(Kl) + boff;

    // S ownership: rows r0, r0+8; cols nb*8 + 2*tq + {0,1}
    const int g = lane >> 2, tq = lane & 3;
    const int r0 = mb * 16 + g;

    // PV layout
    const int m0 = (tid >> 3) * 4, n0o = (tid & 7) * 14;

    unsigned long long accO[2][14];
#pragma unroll
    for (int p = 0; p < 2; p++)
#pragma unroll
        for (int c = 0; c < 14; c++) accO[p][c] = 0ull;
    float run_m[2] = { -1e30f, -1e30f }, run_s[2] = { 0.f, 0.f };

    int buf = 0;
    for (int kb = 0; kb < NS; kb += FBK) {
#pragma unroll
        for (int t = 0; t < 4; t++) {
            if (kOk[t]) {
                *(uint4*)(Kh + kM[t] * QK_LD + kC[t]) = kregH[t];
                *(uint4*)(Kl + kM[t] * QK_LD + kC[t]) = kregL[t];
            }
        }
        if (tid < FBK) { ckx[tid] = crx; cky[tid] = cry; ckz[tid] = crz; kn2s[tid] = crn; }
        __syncthreads();

        // ---- S = QK^T via 4-term HMMA ----
        float accS[8][4];
#pragma unroll
        for (int nb = 0; nb < 8; nb++)
#pragma unroll
            for (int e = 0; e < 4; e++) accS[nb][e] = 0.f;
#pragma unroll
        for (int ks = 0; ks < 7; ks++) {
            uint32_t ka = (uint32_t)(ks * 32);
            uint32_t ah0, ah1, ah2, ah3, al0, al1, al2, al3;
            ldm_x4(qh_a + ka, ah0, ah1, ah2, ah3);
            ldm_x4(ql_a + ka, al0, al1, al2, al3);
#pragma unroll
            for (int nb = 0; nb < 8; nb++) {
                uint32_t off = (uint32_t)(nb * (8 * QK_LD * 2)) + ka;
                uint32_t bh0, bh1, bl0, bl1;
                ldm_x2(kh_b + off, bh0, bh1);
                ldm_x2(kl_b + off, bl0, bl1);
                mma16816(accS[nb], ah0, ah1, ah2, ah3, bh0, bh1);
                mma16816(accS[nb], al0, al1, al2, al3, bh0, bh1);
                mma16816(accS[nb], ah0, ah1, ah2, ah3, bl0, bl1);
                mma16816(accS[nb], al0, al1, al2, al3, bl0, bl1);
            }
        }

        // ---- prefetch next tile ----
        const int kb2 = kb + FBK;
        if (kb2 < NS) {
            float* Vnext = Vs0 + (buf ^ 1) * 64 * VS_LD;
#pragma unroll
            for (int t = 0; t < 4; t++) {
                if (kOk[t]) {
                    kregH[t] = *(const uint4*)(KhG + (size_t)(kb2 + kM[t]) * NCD + kC[t]);
                    kregL[t] = *(const uint4*)(KlG + (size_t)(kb2 + kM[t]) * NCD + kC[t]);
                }
            }
#pragma unroll
            for (int t = 0; t < 7; t++)
                cpasync16(smaddr(Vnext + lKey[t] * VS_LD + lC4[t]),
                          Vg + (size_t)(kb2 + lKey[t]) * NCD + lC4[t]);
            if (tid < FBK) {
                crx = coords[((size_t)b * NS + kb2 + tid) * 3 + 0];
                cry = coords[((size_t)b * NS + kb2 + tid) * 3 + 1];
                crz = coords[((size_t)b * NS + kb2 + tid) * 3 + 2];
                crn = g_kn2[bh * NS + kb2 + tid];
            }
        }
        CP_COMMIT();

        // ---- bias + mask epilogue (rows r0, r0+8) ----
        float qx0 = cqx[r0], qy0 = cqy[r0], qz0 = cqz[r0], qn0 = qn2s[r0];
        float qx1 = cqx[r0 + 8], qy1 = cqy[r0 + 8], qz1 = cqz[r0 + 8], qn1 = qn2s[r0 + 8];
#pragma unroll
        for (int nb = 0; nb < 8; nb++) {
#pragma unroll
            for (int j = 0; j < 2; j++) {
                int gk = nb * 8 + 2 * tq + j;
                float kx = ckx[gk], ky = cky[gk], kz = ckz[gk], knn = kn2s[gk];
                float dx = qx0 - kx, dy = qy0 - ky, dz = qz0 - kz;
                float d2 = fmaf(dx, dx, fmaf(dy, dy, dz * dz));
                float d = sqrtf(d2);
                int idx = 0;
#pragma unroll
                for (int st = 32; st > 0; st >>= 1)
                    if (kn[idx + st] <= d) idx += st;
                float bias = fmaf(al[idx], d, be[idx]) - 0.5f * (qn0 + knn);
                accS[nb][j] = (d2 < 225.f) ? accS[nb][j] + bias : -1e9f;
                dx = qx1 - kx; dy = qy1 - ky; dz = qz1 - kz;
                d2 = fmaf(dx, dx, fmaf(dy, dy, dz * dz));
                d = sqrtf(d2);
                idx = 0;
#pragma unroll
                for (int st = 32; st > 0; st >>= 1)
                    if (kn[idx + st] <= d) idx += st;
                bias = fmaf(al[idx], d, be[idx]) - 0.5f * (qn1 + knn);
                accS[nb][2 + j] = (d2 < 225.f) ? accS[nb][2 + j] + bias : -1e9f;
            }
        }

        // ---- online softmax per row (quad-shared max, per-thread partial sum) ----
#pragma unroll
        for (int idx = 0; idx < 2; idx++) {
            float mx = -1e30f;
#pragma unroll
            for (int nb = 0; nb < 8; nb++)
                mx = fmaxf(mx, fmaxf(accS[nb][2 * idx], accS[nb][2 * idx + 1]));
            mx = fmaxf(mx, __shfl_xor_sync(0xffffffffu, mx, 1));
            mx = fmaxf(mx, __shfl_xor_sync(0xffffffffu, mx, 2));
            float nm = fmaxf(run_m[idx], mx);
            float sc = __expf(run_m[idx] - nm);
            float ts = 0.f;
            int rr = r0 + 8 * idx;
#pragma unroll
            for (int nb = 0; nb < 8; nb++) {
#pragma unroll
                for (int j = 0; j < 2; j++) {
                    float p = __expf(accS[nb][2 * idx + j] - nm);
                    ts += p;
                    Ps[(nb * 8 + 2 * tq + j) * PS_LD + rr] = p;
                }
            }
            run_s[idx] = run_s[idx] * sc + ts;
            run_m[idx] = nm;
            if (tq == 0) rowsc[rr] = sc;
        }
        CP_WAIT1();
        __syncthreads();   // Ps + rowsc + V(current) visible

        // ---- PV: scale accO by row scale, then accumulate ----
        {
            unsigned long long s0 = pack2(rowsc[m0], rowsc[m0 + 1]);
            unsigned long long s1 = pack2(rowsc[m0 + 2], rowsc[m0 + 3]);
#pragma unroll
            for (int c = 0; c < 14; c++) { mul2(accO[0][c], s0); mul2(accO[1][c], s1); }
        }
        const float* Vs = Vs0 + buf * 64 * VS_LD;
        const float* pb = Ps + m0;
        const float* vb = Vs + n0o;
#pragma unroll 2
        for (int kk = 0; kk < FBK; kk++) {
            ulonglong2 pq = *(const ulonglong2*)(pb + kk * PS_LD);
            const float* vr = vb + kk * VS_LD;
#pragma unroll
            for (int c = 0; c < 14; c++) {
                unsigned long long bd = dup2(vr[c]);
                ffma2(accO[0][c], pq.x, bd);
                ffma2(accO[1][c], pq.y, bd);
            }
        }
        buf ^= 1;
    }

    // ---- final: row sums -> rowsc = 1/sum ----
    __syncthreads();   // all PV done reading rowsc before overwrite
#pragma unroll
    for (int idx = 0; idx < 2; idx++) {
        float s = run_s[idx];
        s += __shfl_xor_sync(0xffffffffu, s, 1);
        s += __shfl_xor_sync(0xffffffffu, s, 2);
        if (tq == 0) rowsc[r0 + 8 * idx] = 1.0f / s;
    }
    __syncthreads();

    // ---- output scatter (PV layout) ----
#pragma unroll
    for (int p = 0; p < 2; p++) {
#pragma unroll
        for (int i = 0; i < 2; i++) {
            int r = m0 + 2 * p + i;
            float f = rowsc[r];
            size_t base = (size_t)(b * NS + rb + r) * ATT_W;
#pragma unroll
            for (int c = 0; c < 14; c++) {
                int col = n0o + c;
                int cc = (col < 64) ? (h * 64 + col) : (512 + h * 48 + (col - 64));
                float o0, o1; unpk(accO[p][c], o0, o1);
                g_att[base + cc] = (i == 0 ? o0 : o1) * f;
            }
        }
    }
}

// ---------------- Coords update ----------------
__global__ void k_coords(const float* __restrict__ coords, float* __restrict__ outc) {
    int row = blockIdx.x, t = threadIdx.x;
    const float* ap = g_att + (size_t)row * ATT_W + 512;
    __shared__ float sx[128], sy[128], sz[128];
    sx[t] = ap[t * 3 + 0]; sy[t] = ap[t * 3 + 1]; sz[t] = ap[t * 3 + 2];
    __syncthreads();
    for (int s = 64; s > 0; s >>= 1) {
        if (t < s) { sx[t] += sx[t + s]; sy[t] += sy[t + s]; sz[t] += sz[t + s]; }
        __syncthreads();
    }
    if (t == 0) {
        outc[row * 3 + 0] = coords[row * 3 + 0] + sx[0] * (0.1f / 128.f);
        outc[row * 3 + 1] = coords[row * 3 + 1] + sy[0] * (0.1f / 128.f);
        outc[row * 3 + 2] = coords[row * 3 + 2] + sz[0] * (0.1f / 128.f);
    }
}

// ---------------- Launch ----------------
extern "C" void kernel_launch(void* const* d_in, const int* in_sizes, int n_in,
                              void* d_out, int out_size) {
    const float* x      = (const float*)d_in[0];
    const float* coords = (const float*)d_in[1];
    const float* Wq     = (const float*)d_in[2];
    const float* Wk     = (const float*)d_in[3];
    const float* Wv     = (const float*)d_in[4];
    const float* Wqp    = (const float*)d_in[5];
    const float* bqp    = (const float*)d_in[6];
    const float* Wkp    = (const float*)d_in[7];
    const float* bkp    = (const float*)d_in[8];
    const float* Wvp    = (const float*)d_in[9];
    const float* bvp    = (const float*)d_in[10];
    const float* Wd1    = (const float*)d_in[11];
    const float* bd1    = (const float*)d_in[12];
    const float* Wd2    = (const float*)d_in[13];
    const float* bd2    = (const float*)d_in[14];
    const float* Wo     = (const float*)d_in[15];
    const float* bo     = (const float*)d_in[16];
    const float* g1     = (const float*)d_in[17];
    const float* b1     = (const float*)d_in[18];
    const float* g2     = (const float*)d_in[19];
    const float* b2     = (const float*)d_in[20];
    float* out = (float*)d_out;

    float *p_xn, *p_att, *p_pre;
    cudaGetSymbolAddress((void**)&p_xn,  g_xn);
    cudaGetSymbolAddress((void**)&p_att, g_att);
    cudaGetSymbolAddress((void**)&p_pre, g_pre);

    const int smem_attn = (2 * 128 * QK_LD + 2 * 64 * QK_LD) * 2 +
                          (2 * 64 * VS_LD + 64 * PS_LD + 4 * FBM + 4 * FBK +
                           64 + 33 + 33 + 128) * 4;
    cudaFuncSetAttribute(k_attn, cudaFuncAttributeMaxDynamicSharedMemorySize, smem_attn);

    k_ln<<<NROWS, 256>>>(x, nullptr, g1, b1, p_xn);
    k_proj<<<dim3(NCAT / 64, NROWS / 64), 256>>>(coords, Wq, Wk, Wv, Wqp, Wkp, Wvp,
                                                 bqp, bkp, bvp);
    k_norms<<<NBH * NS / 8, 256>>>();
    k_attn<<<dim3(NS / FBM, NBH), 256, smem_attn>>>(coords, Wd1, bd1, Wd2, bd2);
    gemm_out<<<dim3(ND / 64, NROWS / 64), 256>>>(p_att, Wo, bo, p_pre);
    k_ln<<<NROWS, 256>>>(x, p_pre, g2, b2, out);
    k_coords<<<NROWS, 128>>>(coords, out + (size_t)NROWS * ND);
}